// round 16
// baseline (speedup 1.0000x reference)
#include <cuda_runtime.h>
#include <cuda_fp16.h>
#include <cstdint>

#define Bb 512
#define Tt 512
#define Ff 32
#define Hh 128
#define Ee 64

// producer (layer1) smem: WS = lo-weight frags [16 warps][20 slots][32 lanes] uint4
#define WS_U4   (16*20*32)            // 10240 uint4 = 163840 B
#define BUF1R   (10*32)               // 320 uint4 per B buffer (10 kf)
#define DYN_BYTES ((WS_U4 + 2*BUF1R)*16)   // 174080
// consumer (layer2) B buffers
#define NKF2 12
#define BUF2 (NKF2*32)                // 384 uint4 per buffer

__device__ uint32_t g_seq1[(size_t)Tt*Bb*Hh];   // layer-1 h packed (hi | lo<<16) fp16
__device__ int g_flag[64];                      // per batch-group completed-step count

// ---------------- helpers ----------------
__device__ __forceinline__ uint32_t smem_u32(const void* p) {
    uint32_t a;
    asm("{ .reg .u64 t; cvta.to.shared.u64 t, %1; cvt.u32.u64 %0, t; }" : "=r"(a) : "l"(p));
    return a;
}
__device__ __forceinline__ void mma16816(float* d, const uint32_t* a, uint32_t b0, uint32_t b1) {
    asm("mma.sync.aligned.m16n8k16.row.col.f32.f16.f16.f32 "
        "{%0,%1,%2,%3}, {%4,%5,%6,%7}, {%8,%9}, {%0,%1,%2,%3};"
        : "+f"(d[0]), "+f"(d[1]), "+f"(d[2]), "+f"(d[3])
        : "r"(a[0]), "r"(a[1]), "r"(a[2]), "r"(a[3]), "r"(b0), "r"(b1));
}
__device__ __forceinline__ void splith(float v, __half& hi, __half& lo) {
    hi = __float2half_rn(v);
    lo = __float2half_rn(v - __half2float(hi));
}
__device__ __forceinline__ uint32_t pkh(__half a, __half b) {
    return (uint32_t)__half_as_ushort(a) | ((uint32_t)__half_as_ushort(b) << 16);
}
// byte offset of value (n, k) inside a fragment-packed buffer
__device__ __forceinline__ int bf_off(int n, int k) {
    int kf = k >> 4, r = k & 15;
    return ((kf * 8 + n) * 4 + ((r & 7) >> 1)) * 16 + (r >> 3) * 4 + (r & 1) * 2;
}
__device__ __forceinline__ void st_release(int* p, int v) {
    asm volatile("st.release.gpu.s32 [%0], %1;" :: "l"(p), "r"(v) : "memory");
}
__device__ __forceinline__ int ld_acquire(const int* p) {
    int v;
    asm volatile("ld.acquire.gpu.s32 %0, [%1];" : "=r"(v) : "l"(p) : "memory");
    return v;
}
__device__ __forceinline__ void wait_flag(const int* p, int need) {
    while (ld_acquire(p) < need) { }
}
// single-MUFU activations
__device__ __forceinline__ float tanh_(float z) {
    float r;
    asm("tanh.approx.f32 %0, %1;" : "=f"(r) : "f"(z));
    return r;
}
__device__ __forceinline__ float sigm(float z) {
    return fmaf(tanh_(0.5f * z), 0.5f, 0.5f);
}

__global__ void flags_reset_k() {
    if (threadIdx.x < 64) g_flag[threadIdx.x] = 0;
}

// ---------------------------------------------------------------------------
// Fused: CTAs 0..63 = layer-1 producers (8 batch, ALL 512 gates);
//        CTAs 64..127 = layer-2 consumers (8 batch), gated by g_flag.
// ---------------------------------------------------------------------------
__global__ void __launch_bounds__(512, 1)
fused_lstm(const float* __restrict__ x,
           const float* __restrict__ Wih1, const float* __restrict__ Whh1,
           const float* __restrict__ bih1, const float* __restrict__ bhh1,
           const float* __restrict__ Wih2, const float* __restrict__ Whh2,
           const float* __restrict__ bih2, const float* __restrict__ bhh2,
           float* __restrict__ out)
{
    extern __shared__ uint4 dyn[];
    const int tid = threadIdx.x;
    const int lane = tid & 31, warp = tid >> 5;
    const int tg = lane & 3, gid = lane >> 2;

    if (blockIdx.x < 64) {
        // ===================== LAYER-1 PRODUCER =====================
        uint4* WS = dyn;                    // lo-weight frags
        uint4* BF = dyn + WS_U4;            // 2 x BUF1R activation buffers
        char*  bfb = (char*)BF;
        const int r0 = blockIdx.x * 8;
        const int u = warp * 8 + gid;       // this thread's hidden unit

        // zero B buffers
        for (int i = tid; i < 2 * BUF1R; i += 512) BF[i] = make_uint4(0, 0, 0, 0);

        // weights: hi in regs (Ahi[kf*2+rt]), lo into WS
        uint32_t Ahi[20][4];
#pragma unroll
        for (int kf = 0; kf < 10; kf++) {
            int k0 = kf * 16 + tg * 2;
#pragma unroll
            for (int rt = 0; rt < 2; rt++) {
                uint32_t lo4[4];
#pragma unroll
                for (int qq = 0; qq < 4; qq++) {
                    int hp = qq & 1;
                    int kk = k0 + (qq >> 1) * 8;
                    int gate = 2 * rt + hp;
                    int R = gate * Hh + u;
                    float w0 = (kk < Hh) ? Whh1[R * Hh + kk] : Wih1[R * Ff + (kk - Hh)];
                    float w1 = (kk + 1 < Hh) ? Whh1[R * Hh + kk + 1] : Wih1[R * Ff + (kk + 1 - Hh)];
                    __half h0, l0, h1, l1;
                    splith(w0, h0, l0);
                    splith(w1, h1, l1);
                    Ahi[kf * 2 + rt][qq] = pkh(h0, h1);
                    lo4[qq] = pkh(l0, l1);
                }
                WS[((warp * 20 + kf * 2 + rt) * 32 + lane)] =
                    make_uint4(lo4[0], lo4[1], lo4[2], lo4[3]);
            }
        }

        const float bi_ = bih1[u] + bhh1[u];
        const float bf_ = bih1[Hh + u] + bhh1[Hh + u];
        const float bg_ = bih1[2 * Hh + u] + bhh1[2 * Hh + u];
        const float bo_ = bih1[3 * Hh + u] + bhh1[3 * Hh + u];

        const int bA = 2 * tg, bB = 2 * tg + 1;     // this thread's 2 batch cols
        const int offA = bf_off(bA, u), offB = bf_off(bB, u);

        // x loaders: tid<256 -> (batch xb 0..7, feature xf 0..31)
        const int xb = tid >> 5, xf = tid & 31;
        const int xOff = bf_off(xb, Hh + xf);
        float xn = 0.0f;
        if (tid < 256) {
            float x0 = x[((size_t)(r0 + xb) * Tt + 0) * Ff + xf];
            __half xh, xl;
            splith(x0, xh, xl);
            *(__half*)(bfb + xOff) = xh;
            *(__half*)(bfb + xOff + 8) = xl;
            xn = x[((size_t)(r0 + xb) * Tt + 1) * Ff + xf];
        }
        __syncthreads();

        float cstA = 0.0f, cstB = 0.0f;
        const uint4* bfq = BF + (gid * 4 + tg);
        const uint4* wsp = WS + (warp * 20) * 32 + lane;

        for (int t = 0; t < Tt; t++) {
            const int cur = t & 1, nb = cur ^ 1;
            const uint4* bv = bfq + cur * BUF1R;

            // 4 independent accumulator chains (kf parity split): 15 deep each
            float d0a[4] = {0.f, 0.f, 0.f, 0.f};
            float d1a[4] = {0.f, 0.f, 0.f, 0.f};
            float d0b[4] = {0.f, 0.f, 0.f, 0.f};
            float d1b[4] = {0.f, 0.f, 0.f, 0.f};
#pragma unroll
            for (int kp = 0; kp < 5; kp++) {
                const int ke = 2 * kp, ko = 2 * kp + 1;
                uint4 ve  = bv[ke * 32];
                uint4 vo  = bv[ko * 32];
                uint4 le0 = wsp[(ke * 2 + 0) * 32];
                uint4 le1 = wsp[(ke * 2 + 1) * 32];
                uint4 lo0 = wsp[(ko * 2 + 0) * 32];
                uint4 lo1 = wsp[(ko * 2 + 1) * 32];
                mma16816(d0a, Ahi[ke * 2 + 0], ve.x, ve.y);
                mma16816(d0b, Ahi[ko * 2 + 0], vo.x, vo.y);
                mma16816(d1a, Ahi[ke * 2 + 1], ve.x, ve.y);
                mma16816(d1b, Ahi[ko * 2 + 1], vo.x, vo.y);
                mma16816(d0a, (const uint32_t*)&le0, ve.x, ve.y);
                mma16816(d0b, (const uint32_t*)&lo0, vo.x, vo.y);
                mma16816(d1a, (const uint32_t*)&le1, ve.x, ve.y);
                mma16816(d1b, (const uint32_t*)&lo1, vo.x, vo.y);
                mma16816(d0a, Ahi[ke * 2 + 0], ve.z, ve.w);
                mma16816(d0b, Ahi[ko * 2 + 0], vo.z, vo.w);
                mma16816(d1a, Ahi[ke * 2 + 1], ve.z, ve.w);
                mma16816(d1b, Ahi[ko * 2 + 1], vo.z, vo.w);
            }

            // cell A (batch bA): gates i,f from tile0; g,o from tile1
            float ziA = d0a[0] + d0b[0] + bi_, zfA = d0a[2] + d0b[2] + bf_;
            float zgA = d1a[0] + d1b[0] + bg_, zoA = d1a[2] + d1b[2] + bo_;
            cstA = sigm(zfA) * cstA + sigm(ziA) * tanh_(zgA);
            float hA = sigm(zoA) * tanh_(cstA);
            // cell B (batch bB)
            float ziB = d0a[1] + d0b[1] + bi_, zfB = d0a[3] + d0b[3] + bf_;
            float zgB = d1a[1] + d1b[1] + bg_, zoB = d1a[3] + d1b[3] + bo_;
            cstB = sigm(zfB) * cstB + sigm(ziB) * tanh_(zgB);
            float hB = sigm(zoB) * tanh_(cstB);

            __half hAh, hAl, hBh, hBl;
            splith(hA, hAh, hAl);
            splith(hB, hBh, hBl);
            g_seq1[((size_t)t * Bb + r0 + bA) * Hh + u] = pkh(hAh, hAl);
            g_seq1[((size_t)t * Bb + r0 + bB) * Hh + u] = pkh(hBh, hBl);

            if (t + 1 < Tt) {
                char* dst = bfb + nb * (BUF1R * 16);
                *(__half*)(dst + offA) = hAh;
                *(__half*)(dst + offA + 8) = hAl;
                *(__half*)(dst + offB) = hBh;
                *(__half*)(dst + offB + 8) = hBl;
                if (tid < 256) {
                    __half xh, xl;
                    splith(xn, xh, xl);
                    *(__half*)(dst + xOff) = xh;
                    *(__half*)(dst + xOff + 8) = xl;
                    xn = (t + 2 < Tt) ? x[((size_t)(r0 + xb) * Tt + t + 2) * Ff + xf] : 0.0f;
                }
            }
            __syncthreads();
            if (tid == 0) st_release(&g_flag[blockIdx.x], t + 1);
        }
    } else {
        // ===================== LAYER-2 CONSUMER =====================
        uint4* BF2 = dyn;                   // 2 x BUF2
        char*  bfb = (char*)BF2;
        const int bg = blockIdx.x - 64;
        const int r0 = bg * 8;
        const int* flag = &g_flag[bg];
        const int q = gid >> 2, m = gid & 3;

        for (int i = tid; i < 2 * BUF2; i += 512) BF2[i] = make_uint4(0, 0, 0, 0);

        uint32_t Ahi[12][4], Alo[12][4];
#pragma unroll
        for (int kf = 0; kf < 12; kf++) {
            int k0 = kf * 16 + tg * 2;
#pragma unroll
            for (int qq = 0; qq < 4; qq++) {
                int rslot = gid + (qq & 1) * 8;
                int kk = k0 + (qq >> 1) * 8;
                int ul = warp * 4 + (rslot & 3);
                int gate = 2 * (rslot >> 3) + ((rslot >> 2) & 1);
                int R = gate * Ee + ul;
                float w0 = (kk < Hh) ? Wih2[R * Hh + kk] : Whh2[R * Ee + (kk - Hh)];
                float w1 = (kk + 1 < Hh) ? Wih2[R * Hh + kk + 1] : Whh2[R * Ee + (kk + 1 - Hh)];
                __half h0, l0, h1, l1;
                splith(w0, h0, l0);
                splith(w1, h1, l1);
                Ahi[kf][qq] = pkh(h0, h1);
                Alo[kf][qq] = pkh(l0, l1);
            }
        }

        const int u = warp * 4 + m;
        const int c = tg * 2 + q;
        const float bi_ = bih2[u] + bhh2[u];
        const float bf_ = bih2[Ee + u] + bhh2[Ee + u];
        const float bg_ = bih2[2 * Ee + u] + bhh2[2 * Ee + u];
        const float bo_ = bih2[3 * Ee + u] + bhh2[3 * Ee + u];

        const int cellOff = bf_off(c, Hh + u);
        const int lk = tid & 127, lb = tid >> 7;
        const int lOff0 = bf_off(lb, lk);
        const int lOff1 = bf_off(lb + 4, lk);

        __syncthreads();   // zero done
        wait_flag(flag, 2);   // seq1[0], seq1[1] available
        uint32_t p0 = g_seq1[((size_t)0 * Bb + r0 + lb) * Hh + lk];
        uint32_t p1 = g_seq1[((size_t)0 * Bb + r0 + lb + 4) * Hh + lk];
        *(__half*)(bfb + lOff0)     = __ushort_as_half((uint16_t)(p0 & 0xFFFF));
        *(__half*)(bfb + lOff0 + 8) = __ushort_as_half((uint16_t)(p0 >> 16));
        *(__half*)(bfb + lOff1)     = __ushort_as_half((uint16_t)(p1 & 0xFFFF));
        *(__half*)(bfb + lOff1 + 8) = __ushort_as_half((uint16_t)(p1 >> 16));
        p0 = g_seq1[((size_t)1 * Bb + r0 + lb) * Hh + lk];
        p1 = g_seq1[((size_t)1 * Bb + r0 + lb + 4) * Hh + lk];
        __syncthreads();

        float cst = 0.0f, hlast = 0.0f;
        const uint4* bfq = BF2 + (gid * 4 + tg);

        for (int t = 0; t < Tt; t++) {
            const int cur = t & 1;
            const uint4* bv = bfq + cur * BUF2;
            float dh[4] = {0.f,0.f,0.f,0.f}, dm[4] = {0.f,0.f,0.f,0.f}, dl[4] = {0.f,0.f,0.f,0.f};
#pragma unroll
            for (int kf = 0; kf < 12; kf++) {
                uint4 v = bv[kf * 32];
                mma16816(dh, Ahi[kf], v.x, v.y);
                mma16816(dm, Alo[kf], v.x, v.y);
                mma16816(dl, Ahi[kf], v.z, v.w);
            }
            float d0 = dh[0] + dm[0] + dl[0];
            float d1 = dh[1] + dm[1] + dl[1];
            float d2 = dh[2] + dm[2] + dl[2];
            float d3 = dh[3] + dm[3] + dl[3];

            float X = __shfl_xor_sync(0xFFFFFFFFu, q ? d0 : d1, 16);
            float Y = __shfl_xor_sync(0xFFFFFFFFu, q ? d2 : d3, 16);
            float zi = (q ? X : d0) + bi_;
            float zf = (q ? d1 : X) + bf_;
            float zg = (q ? Y : d2) + bg_;
            float zo = (q ? d3 : Y) + bo_;

            cst = sigm(zf) * cst + sigm(zi) * tanh_(zg);
            hlast = sigm(zo) * tanh_(cst);

            if (t + 1 < Tt) {
                const int nb = cur ^ 1;
                char* dst = bfb + nb * (BUF2 * 16);
                __half hh, hl;
                splith(hlast, hh, hl);
                *(__half*)(dst + cellOff) = hh;
                *(__half*)(dst + cellOff + 8) = hl;
                *(__half*)(dst + lOff0)     = __ushort_as_half((uint16_t)(p0 & 0xFFFF));
                *(__half*)(dst + lOff0 + 8) = __ushort_as_half((uint16_t)(p0 >> 16));
                *(__half*)(dst + lOff1)     = __ushort_as_half((uint16_t)(p1 & 0xFFFF));
                *(__half*)(dst + lOff1 + 8) = __ushort_as_half((uint16_t)(p1 >> 16));
                if (t + 2 < Tt) {
                    wait_flag(flag, t + 3);   // seq1[t+2] published
                    p0 = g_seq1[((size_t)(t + 2) * Bb + r0 + lb) * Hh + lk];
                    p1 = g_seq1[((size_t)(t + 2) * Bb + r0 + lb + 4) * Hh + lk];
                }
            }
            __syncthreads();
        }
        out[(size_t)(r0 + c) * Ee + u] = hlast;
    }
}

extern "C" void kernel_launch(void* const* d_in, const int* in_sizes, int n_in,
                              void* d_out, int out_size)
{
    const float* x    = (const float*)d_in[0];
    const float* Wih1 = (const float*)d_in[1];
    const float* Whh1 = (const float*)d_in[2];
    const float* bih1 = (const float*)d_in[3];
    const float* bhh1 = (const float*)d_in[4];
    const float* Wih2 = (const float*)d_in[5];
    const float* Whh2 = (const float*)d_in[6];
    const float* bih2 = (const float*)d_in[7];
    const float* bhh2 = (const float*)d_in[8];
    float* out = (float*)d_out;

    cudaFuncSetAttribute(fused_lstm, cudaFuncAttributeMaxDynamicSharedMemorySize, DYN_BYTES);

    flags_reset_k<<<1, 64>>>();
    fused_lstm<<<128, 512, DYN_BYTES>>>(x, Wih1, Whh1, bih1, bhh1,
                                        Wih2, Whh2, bih2, bhh2, out);
}

// round 17
// speedup vs baseline: 1.1615x; 1.1615x over previous
#include <cuda_runtime.h>
#include <cuda_fp16.h>
#include <cstdint>

#define Bb 512
#define Tt 512
#define Ff 32
#define Hh 128
#define Ee 64

#define BUF1R   (10*32)               // 320 uint4 per producer B buffer (10 kf)
#define NKF2 12
#define BUF2 (NKF2*32)                // 384 uint4 per consumer B buffer
#define DYN_BYTES (2*BUF2*16)         // 12288 (max of both branches)

__device__ uint32_t g_seq1[(size_t)Tt*Bb*Hh];   // layer-1 h packed (hi | lo<<16) fp16
__device__ int g_flag[64];                      // per batch-group completed-step count

// ---------------- helpers ----------------
__device__ __forceinline__ void mma16816(float* d, const uint32_t* a, uint32_t b0, uint32_t b1) {
    asm("mma.sync.aligned.m16n8k16.row.col.f32.f16.f16.f32 "
        "{%0,%1,%2,%3}, {%4,%5,%6,%7}, {%8,%9}, {%0,%1,%2,%3};"
        : "+f"(d[0]), "+f"(d[1]), "+f"(d[2]), "+f"(d[3])
        : "r"(a[0]), "r"(a[1]), "r"(a[2]), "r"(a[3]), "r"(b0), "r"(b1));
}
__device__ __forceinline__ void splith(float v, __half& hi, __half& lo) {
    hi = __float2half_rn(v);
    lo = __float2half_rn(v - __half2float(hi));
}
__device__ __forceinline__ uint32_t pkh(__half a, __half b) {
    return (uint32_t)__half_as_ushort(a) | ((uint32_t)__half_as_ushort(b) << 16);
}
// byte offset of value (n, k) inside a fragment-packed buffer
__device__ __forceinline__ int bf_off(int n, int k) {
    int kf = k >> 4, r = k & 15;
    return ((kf * 8 + n) * 4 + ((r & 7) >> 1)) * 16 + (r >> 3) * 4 + (r & 1) * 2;
}
__device__ __forceinline__ void st_release(int* p, int v) {
    asm volatile("st.release.gpu.s32 [%0], %1;" :: "l"(p), "r"(v) : "memory");
}
__device__ __forceinline__ int ld_acquire(const int* p) {
    int v;
    asm volatile("ld.acquire.gpu.s32 %0, [%1];" : "=r"(v) : "l"(p) : "memory");
    return v;
}
__device__ __forceinline__ void wait_flag(const int* p, int need) {
    while (ld_acquire(p) < need) { }
}
// single-MUFU activations
__device__ __forceinline__ float tanh_(float z) {
    float r;
    asm("tanh.approx.f32 %0, %1;" : "=f"(r) : "f"(z));
    return r;
}
__device__ __forceinline__ float sigm(float z) {
    return fmaf(tanh_(0.5f * z), 0.5f, 0.5f);
}

__global__ void flags_reset_k() {
    if (threadIdx.x < 64) g_flag[threadIdx.x] = 0;
}

// ---------------------------------------------------------------------------
// Fused: CTAs 0..63 = layer-1 producers (8 batch, ALL 512 gates);
//        CTAs 64..127 = layer-2 consumers (8 batch), gated by g_flag.
// 2-term scheme: gates = fp16(W) x (a_hi + a_lo).
// ---------------------------------------------------------------------------
__global__ void __launch_bounds__(512, 1)
fused_lstm(const float* __restrict__ x,
           const float* __restrict__ Wih1, const float* __restrict__ Whh1,
           const float* __restrict__ bih1, const float* __restrict__ bhh1,
           const float* __restrict__ Wih2, const float* __restrict__ Whh2,
           const float* __restrict__ bih2, const float* __restrict__ bhh2,
           float* __restrict__ out)
{
    extern __shared__ uint4 dyn[];
    const int tid = threadIdx.x;
    const int lane = tid & 31, warp = tid >> 5;
    const int tg = lane & 3, gid = lane >> 2;

    if (blockIdx.x < 64) {
        // ===================== LAYER-1 PRODUCER =====================
        uint4* BF = dyn;                    // 2 x BUF1R activation buffers
        char*  bfb = (char*)BF;
        const int r0 = blockIdx.x * 8;
        const int u = warp * 8 + gid;       // this thread's hidden unit

        // zero B buffers
        for (int i = tid; i < 2 * BUF1R; i += 512) BF[i] = make_uint4(0, 0, 0, 0);

        // weights: fp16 hi in regs only
        uint32_t Ahi[20][4];
#pragma unroll
        for (int kf = 0; kf < 10; kf++) {
            int k0 = kf * 16 + tg * 2;
#pragma unroll
            for (int rt = 0; rt < 2; rt++) {
#pragma unroll
                for (int qq = 0; qq < 4; qq++) {
                    int hp = qq & 1;
                    int kk = k0 + (qq >> 1) * 8;
                    int gate = 2 * rt + hp;
                    int R = gate * Hh + u;
                    float w0 = (kk < Hh) ? Whh1[R * Hh + kk] : Wih1[R * Ff + (kk - Hh)];
                    float w1 = (kk + 1 < Hh) ? Whh1[R * Hh + kk + 1] : Wih1[R * Ff + (kk + 1 - Hh)];
                    Ahi[kf * 2 + rt][qq] = pkh(__float2half_rn(w0), __float2half_rn(w1));
                }
            }
        }

        const float bi_ = bih1[u] + bhh1[u];
        const float bf_ = bih1[Hh + u] + bhh1[Hh + u];
        const float bg_ = bih1[2 * Hh + u] + bhh1[2 * Hh + u];
        const float bo_ = bih1[3 * Hh + u] + bhh1[3 * Hh + u];

        const int bA = 2 * tg, bB = 2 * tg + 1;     // this thread's 2 batch cols
        const int offA = bf_off(bA, u), offB = bf_off(bB, u);

        // x loaders: tid<256 -> (batch xb 0..7, feature xf 0..31)
        const int xb = tid >> 5, xf = tid & 31;
        const int xOff = bf_off(xb, Hh + xf);
        float xn = 0.0f;
        if (tid < 256) {
            float x0 = x[((size_t)(r0 + xb) * Tt + 0) * Ff + xf];
            __half xh, xl;
            splith(x0, xh, xl);
            *(__half*)(bfb + xOff) = xh;
            *(__half*)(bfb + xOff + 8) = xl;
            xn = x[((size_t)(r0 + xb) * Tt + 1) * Ff + xf];
        }
        __syncthreads();

        float cstA = 0.0f, cstB = 0.0f;
        const uint4* bfq = BF + (gid * 4 + tg);

        for (int t = 0; t < Tt; t++) {
            const int cur = t & 1, nb = cur ^ 1;
            const uint4* bv = bfq + cur * BUF1R;

            float d0[4] = {0.f, 0.f, 0.f, 0.f};
            float d1[4] = {0.f, 0.f, 0.f, 0.f};
#pragma unroll
            for (int kf = 0; kf < 10; kf++) {
                uint4 v = bv[kf * 32];
                mma16816(d0, Ahi[kf * 2 + 0], v.x, v.y);
                mma16816(d1, Ahi[kf * 2 + 1], v.x, v.y);
                mma16816(d0, Ahi[kf * 2 + 0], v.z, v.w);
                mma16816(d1, Ahi[kf * 2 + 1], v.z, v.w);
            }

            // cell A (batch bA): gates i,f from tile0; g,o from tile1
            float ziA = d0[0] + bi_, zfA = d0[2] + bf_;
            float zgA = d1[0] + bg_, zoA = d1[2] + bo_;
            cstA = sigm(zfA) * cstA + sigm(ziA) * tanh_(zgA);
            float hA = sigm(zoA) * tanh_(cstA);
            // cell B (batch bB)
            float ziB = d0[1] + bi_, zfB = d0[3] + bf_;
            float zgB = d1[1] + bg_, zoB = d1[3] + bo_;
            cstB = sigm(zfB) * cstB + sigm(ziB) * tanh_(zgB);
            float hB = sigm(zoB) * tanh_(cstB);

            __half hAh, hAl, hBh, hBl;
            splith(hA, hAh, hAl);
            splith(hB, hBh, hBl);
            g_seq1[((size_t)t * Bb + r0 + bA) * Hh + u] = pkh(hAh, hAl);
            g_seq1[((size_t)t * Bb + r0 + bB) * Hh + u] = pkh(hBh, hBl);

            if (t + 1 < Tt) {
                char* dst = bfb + nb * (BUF1R * 16);
                *(__half*)(dst + offA) = hAh;
                *(__half*)(dst + offA + 8) = hAl;
                *(__half*)(dst + offB) = hBh;
                *(__half*)(dst + offB + 8) = hBl;
                if (tid < 256) {
                    __half xh, xl;
                    splith(xn, xh, xl);
                    *(__half*)(dst + xOff) = xh;
                    *(__half*)(dst + xOff + 8) = xl;
                    xn = (t + 2 < Tt) ? x[((size_t)(r0 + xb) * Tt + t + 2) * Ff + xf] : 0.0f;
                }
            }
            __syncthreads();
            if (tid == 0) st_release(&g_flag[blockIdx.x], t + 1);
        }
    } else {
        // ===================== LAYER-2 CONSUMER =====================
        uint4* BF2 = dyn;                   // 2 x BUF2
        char*  bfb = (char*)BF2;
        const int bg = blockIdx.x - 64;
        const int r0 = bg * 8;
        const int* flag = &g_flag[bg];
        const int q = gid >> 2, m = gid & 3;

        for (int i = tid; i < 2 * BUF2; i += 512) BF2[i] = make_uint4(0, 0, 0, 0);

        uint32_t Ahi[12][4];
#pragma unroll
        for (int kf = 0; kf < 12; kf++) {
            int k0 = kf * 16 + tg * 2;
#pragma unroll
            for (int qq = 0; qq < 4; qq++) {
                int rslot = gid + (qq & 1) * 8;
                int kk = k0 + (qq >> 1) * 8;
                int ul = warp * 4 + (rslot & 3);
                int gate = 2 * (rslot >> 3) + ((rslot >> 2) & 1);
                int R = gate * Ee + ul;
                float w0 = (kk < Hh) ? Wih2[R * Hh + kk] : Whh2[R * Ee + (kk - Hh)];
                float w1 = (kk + 1 < Hh) ? Wih2[R * Hh + kk + 1] : Whh2[R * Ee + (kk + 1 - Hh)];
                Ahi[kf][qq] = pkh(__float2half_rn(w0), __float2half_rn(w1));
            }
        }

        const int u = warp * 4 + m;
        const int c = tg * 2 + q;
        const float bi_ = bih2[u] + bhh2[u];
        const float bf_ = bih2[Ee + u] + bhh2[Ee + u];
        const float bg_ = bih2[2 * Ee + u] + bhh2[2 * Ee + u];
        const float bo_ = bih2[3 * Ee + u] + bhh2[3 * Ee + u];

        const int cellOff = bf_off(c, Hh + u);
        const int lk = tid & 127, lb = tid >> 7;
        const int lOff0 = bf_off(lb, lk);
        const int lOff1 = bf_off(lb + 4, lk);

        __syncthreads();   // zero done
        wait_flag(flag, 2);   // seq1[0], seq1[1] available
        uint32_t p0 = g_seq1[((size_t)0 * Bb + r0 + lb) * Hh + lk];
        uint32_t p1 = g_seq1[((size_t)0 * Bb + r0 + lb + 4) * Hh + lk];
        *(__half*)(bfb + lOff0)     = __ushort_as_half((uint16_t)(p0 & 0xFFFF));
        *(__half*)(bfb + lOff0 + 8) = __ushort_as_half((uint16_t)(p0 >> 16));
        *(__half*)(bfb + lOff1)     = __ushort_as_half((uint16_t)(p1 & 0xFFFF));
        *(__half*)(bfb + lOff1 + 8) = __ushort_as_half((uint16_t)(p1 >> 16));
        p0 = g_seq1[((size_t)1 * Bb + r0 + lb) * Hh + lk];
        p1 = g_seq1[((size_t)1 * Bb + r0 + lb + 4) * Hh + lk];
        __syncthreads();

        float cst = 0.0f, hlast = 0.0f;
        const uint4* bfq = BF2 + (gid * 4 + tg);

        for (int t = 0; t < Tt; t++) {
            const int cur = t & 1;
            const uint4* bv = bfq + cur * BUF2;
            float dh[4] = {0.f,0.f,0.f,0.f}, dl[4] = {0.f,0.f,0.f,0.f};
#pragma unroll
            for (int kf = 0; kf < 12; kf++) {
                uint4 v = bv[kf * 32];
                mma16816(dh, Ahi[kf], v.x, v.y);
                mma16816(dl, Ahi[kf], v.z, v.w);
            }
            float d0 = dh[0] + dl[0];
            float d1 = dh[1] + dl[1];
            float d2 = dh[2] + dl[2];
            float d3 = dh[3] + dl[3];

            float X = __shfl_xor_sync(0xFFFFFFFFu, q ? d0 : d1, 16);
            float Y = __shfl_xor_sync(0xFFFFFFFFu, q ? d2 : d3, 16);
            float zi = (q ? X : d0) + bi_;
            float zf = (q ? d1 : X) + bf_;
            float zg = (q ? Y : d2) + bg_;
            float zo = (q ? d3 : Y) + bo_;

            cst = sigm(zf) * cst + sigm(zi) * tanh_(zg);
            hlast = sigm(zo) * tanh_(cst);

            if (t + 1 < Tt) {
                const int nb = cur ^ 1;
                char* dst = bfb + nb * (BUF2 * 16);
                __half hh, hl;
                splith(hlast, hh, hl);
                *(__half*)(dst + cellOff) = hh;
                *(__half*)(dst + cellOff + 8) = hl;
                *(__half*)(dst + lOff0)     = __ushort_as_half((uint16_t)(p0 & 0xFFFF));
                *(__half*)(dst + lOff0 + 8) = __ushort_as_half((uint16_t)(p0 >> 16));
                *(__half*)(dst + lOff1)     = __ushort_as_half((uint16_t)(p1 & 0xFFFF));
                *(__half*)(dst + lOff1 + 8) = __ushort_as_half((uint16_t)(p1 >> 16));
                if (t + 2 < Tt) {
                    wait_flag(flag, t + 3);   // seq1[t+2] published
                    p0 = g_seq1[((size_t)(t + 2) * Bb + r0 + lb) * Hh + lk];
                    p1 = g_seq1[((size_t)(t + 2) * Bb + r0 + lb + 4) * Hh + lk];
                }
            }
            __syncthreads();
        }
        out[(size_t)(r0 + c) * Ee + u] = hlast;
    }
}

extern "C" void kernel_launch(void* const* d_in, const int* in_sizes, int n_in,
                              void* d_out, int out_size)
{
    const float* x    = (const float*)d_in[0];
    const float* Wih1 = (const float*)d_in[1];
    const float* Whh1 = (const float*)d_in[2];
    const float* bih1 = (const float*)d_in[3];
    const float* bhh1 = (const float*)d_in[4];
    const float* Wih2 = (const float*)d_in[5];
    const float* Whh2 = (const float*)d_in[6];
    const float* bih2 = (const float*)d_in[7];
    const float* bhh2 = (const float*)d_in[8];
    float* out = (float*)d_out;

    cudaFuncSetAttribute(fused_lstm, cudaFuncAttributeMaxDynamicSharedMemorySize, DYN_BYTES);

    flags_reset_k<<<1, 64>>>();
    fused_lstm<<<128, 512, DYN_BYTES>>>(x, Wih1, Whh1, bih1, bhh1,
                                        Wih2, Whh2, bih2, bhh2, out);
}